// round 15
// baseline (speedup 1.0000x reference)
#include <cuda_runtime.h>
#include <cuda_bf16.h>
#include <math.h>
#include <cstdint>

#define BATCH   4
#define SEQ     2048
#define DMODEL  768
#define NHEADS  12
#define HDIM    64
#define MTOT    (BATCH*SEQ)   /* 8192 */
#define WSZ     (DMODEL*DMODEL)

// Scratch (static device arrays: allocation-free per harness rules)
__device__ float2 g_tbl[SEQ*(HDIM/2)];
__device__ __nv_bfloat16 g_xh[MTOT*DMODEL], g_xl[MTOT*DMODEL];
__device__ __nv_bfloat16 g_wh[4*WSZ],       g_wl[4*WSZ];
__device__ __nv_bfloat16 g_Qh[MTOT*DMODEL], g_Ql[MTOT*DMODEL];
__device__ __nv_bfloat16 g_Kh[MTOT*DMODEL], g_Kl[MTOT*DMODEL];
__device__ __nv_bfloat16 g_Vh[MTOT*DMODEL], g_Vl[MTOT*DMODEL];
__device__ __nv_bfloat16 g_AOh[MTOT*DMODEL], g_AOl[MTOT*DMODEL];

// ===========================================================================
// Helpers
// ===========================================================================
__device__ __forceinline__ uint32_t smem_u32(const void* p) {
    uint32_t a;
    asm("{ .reg .u64 t; cvta.to.shared.u64 t, %1; cvt.u32.u64 %0, t; }" : "=r"(a) : "l"(p));
    return a;
}
__device__ __forceinline__ void ldsm4(uint32_t* r, uint32_t addr) {
    asm volatile("ldmatrix.sync.aligned.m8n8.x4.shared.b16 {%0,%1,%2,%3}, [%4];"
        : "=r"(r[0]), "=r"(r[1]), "=r"(r[2]), "=r"(r[3]) : "r"(addr));
}
__device__ __forceinline__ void ldsm4t(uint32_t* r, uint32_t addr) {
    asm volatile("ldmatrix.sync.aligned.m8n8.x4.trans.shared.b16 {%0,%1,%2,%3}, [%4];"
        : "=r"(r[0]), "=r"(r[1]), "=r"(r[2]), "=r"(r[3]) : "r"(addr));
}
__device__ __forceinline__ void mma16816(float* c, const uint32_t* a, uint32_t b0, uint32_t b1) {
    asm volatile("mma.sync.aligned.m16n8k16.row.col.f32.bf16.bf16.f32 "
        "{%0,%1,%2,%3}, {%4,%5,%6,%7}, {%8,%9}, {%0,%1,%2,%3};"
        : "+f"(c[0]), "+f"(c[1]), "+f"(c[2]), "+f"(c[3])
        : "r"(a[0]), "r"(a[1]), "r"(a[2]), "r"(a[3]), "r"(b0), "r"(b1));
}
__device__ __forceinline__ uint32_t pack2(float x, float y) {
    __nv_bfloat16 hx = __float2bfloat16(x), hy = __float2bfloat16(y);
    return (uint32_t)__bfloat16_as_ushort(hx) | ((uint32_t)__bfloat16_as_ushort(hy) << 16);
}
__device__ __forceinline__ void split2(float x, float y, uint32_t& hi, uint32_t& lo) {
    __nv_bfloat16 hx = __float2bfloat16(x), hy = __float2bfloat16(y);
    hi = (uint32_t)__bfloat16_as_ushort(hx) | ((uint32_t)__bfloat16_as_ushort(hy) << 16);
    lo = pack2(x - __bfloat162float(hx), y - __bfloat162float(hy));
}
__device__ __forceinline__ void cp16(uint32_t dst, const void* src) {
    asm volatile("cp.async.cg.shared.global [%0], [%1], 16;" :: "r"(dst), "l"(src) : "memory");
}
#define CP_COMMIT() asm volatile("cp.async.commit_group;" ::: "memory")
#define CP_WAIT(n)  asm volatile("cp.async.wait_group %0;" :: "n"(n) : "memory")

// ---------------------------------------------------------------------------
// RoPE table (fp64-accurate sincos)
// ---------------------------------------------------------------------------
__global__ void rope_table_kernel()
{
    int idx = blockIdx.x * blockDim.x + threadIdx.x;
    if (idx >= SEQ * (HDIM/2)) return;
    int s = idx >> 5, j = idx & 31;
    float invf = (float)pow(10000.0, -(double)(2*j) / (double)HDIM);
    float angf = (float)s * invf;
    double sn, cs;
    sincos((double)angf, &sn, &cs);
    g_tbl[idx] = make_float2((float)cs, (float)sn);
}

// ---------------------------------------------------------------------------
// hi/lo bf16 splits
// ---------------------------------------------------------------------------
__device__ __forceinline__ void split4v(float4 v, uint2& hi, uint2& lo)
{
    split2(v.x, v.y, hi.x, lo.x);
    split2(v.z, v.w, hi.y, lo.y);
}
__global__ void splitw_kernel(const float* __restrict__ w0, const float* __restrict__ w1,
                              const float* __restrict__ w2, const float* __restrict__ w3)
{
    const int wn4 = WSZ / 4;
    int i = blockIdx.x * blockDim.x + threadIdx.x;
    if (i >= 4 * wn4) return;
    int ws = i / wn4, off = i - ws * wn4;
    const float* src = (ws == 0) ? w0 : (ws == 1) ? w1 : (ws == 2) ? w2 : w3;
    uint2 h, l;
    split4v(((const float4*)src)[off], h, l);
    ((uint2*)g_wh)[i] = h;
    ((uint2*)g_wl)[i] = l;
}
__global__ void splitx_kernel(const float* __restrict__ x)
{
    const int xn4 = MTOT * DMODEL / 4;
    int i = blockIdx.x * blockDim.x + threadIdx.x;
    if (i >= xn4) return;
    uint2 h, l;
    split4v(((const float4*)x)[i], h, l);
    ((uint2*)g_xh)[i] = h;
    ((uint2*)g_xl)[i] = l;
}

// ===========================================================================
// 4-stage cp.async split-bf16 tensor-core GEMM, CTA tile 128x256.
// 8 warps = 2(m) x 4(n), warp tile 64x64 -> 16 ldsm / 96 mma per chunk
// (mma/ldsm = 6). Pass order AhBh -> AlBh -> AhBl keeps peak fragment
// liveness at 3 sets. 1 CTA/SM (regs ~200, smem 147KB).
// FUSED=1: QKV fused, grid (9,64), sec = blockIdx.x/3.
// FUSED=0: WO, grid (3,64), fp32 out.
// ===========================================================================
#define SROW     48
#define A_BUF    (128*SROW)             /* 6144  */
#define B_BUF    (256*SROW)             /* 12288 */
#define STAGE_SZ (2*A_BUF + 2*B_BUF)    /* 36864 */
#define NSTAGE   4
#define NCHUNK   (DMODEL/16)            /* 48    */

template<int FUSED>
__global__ __launch_bounds__(256, 1) void gemm_db_kernel(
    const __nv_bfloat16* __restrict__ Ah, const __nv_bfloat16* __restrict__ Al,
    const __nv_bfloat16* __restrict__ Bh0, const __nv_bfloat16* __restrict__ Bl0,
    __nv_bfloat16* __restrict__ QH, __nv_bfloat16* __restrict__ QL,
    __nv_bfloat16* __restrict__ KH, __nv_bfloat16* __restrict__ KL,
    __nv_bfloat16* __restrict__ VH, __nv_bfloat16* __restrict__ VL,
    float* __restrict__ C)
{
    extern __shared__ __align__(16) char sm[];
    const uint32_t sb = smem_u32(sm);

    const int tid = threadIdx.x;
    const int wid = tid >> 5, lane = tid & 31;
    const int wm  = wid >> 2, wn = wid & 3;       // 2 x 4 warps
    const int m0  = blockIdx.y * 128;

    int sec, nx;
    if (FUSED) { sec = blockIdx.x / 3; nx = blockIdx.x % 3; }
    else       { sec = 0;              nx = blockIdx.x;     }
    const int n0 = nx * 256;
    const __nv_bfloat16* Bh = Bh0 + (size_t)sec * WSZ;
    const __nv_bfloat16* Bl = Bl0 + (size_t)sec * WSZ;

    // Loader: A -> row ar (0..127), 8-col half; B -> row tid (0..255), both halves
    const int ar  = tid >> 1;
    const int ahf = (tid & 1) * 8;
    const size_t aoff = (size_t)(m0 + ar) * DMODEL + ahf;
    const size_t boff = (size_t)(n0 + tid) * DMODEL;
    const uint32_t a_s = (uint32_t)(ar * SROW + ahf * 2);
    const uint32_t b_s = (uint32_t)(tid * SROW);

    const uint32_t a_row  = wm * 64 + (lane & 15);
    const uint32_t a_colb = (lane >> 4) * 16;
    const uint32_t b_row  = wn * 64 + (lane & 7) + ((lane >> 4) << 3);
    const uint32_t b_colb = ((lane >> 3) & 1) * 16;

    float acc[4][8][4] = {};

    #pragma unroll
    for (int s = 0; s < NSTAGE - 1; s++) {        // prologue: chunks 0..2
        const int kc = s * 16;
        const uint32_t base = sb + s * STAGE_SZ;
        cp16(base + a_s,                        Ah + aoff + kc);
        cp16(base + A_BUF + a_s,                Al + aoff + kc);
        cp16(base + 2*A_BUF + b_s,              Bh + boff + kc);
        cp16(base + 2*A_BUF + b_s + 16,         Bh + boff + kc + 8);
        cp16(base + 2*A_BUF + B_BUF + b_s,      Bl + boff + kc);
        cp16(base + 2*A_BUF + B_BUF + b_s + 16, Bl + boff + kc + 8);
        CP_COMMIT();
    }

    for (int c = 0; c < NCHUNK; c++) {
        const uint32_t stb = sb + (uint32_t)(c % NSTAGE) * STAGE_SZ;

        if (c + 2 < NCHUNK)      CP_WAIT(2);
        else if (c + 1 < NCHUNK) CP_WAIT(1);
        else                     CP_WAIT(0);
        __syncthreads();

        // ---- p0: Ah * Bh ----
        uint32_t ah4[4][4], bh4[4][4];
        #pragma unroll
        for (int mf = 0; mf < 4; mf++)
            ldsm4(ah4[mf], stb + (a_row + mf*16) * SROW + a_colb);
        #pragma unroll
        for (int nh = 0; nh < 4; nh++)
            ldsm4(bh4[nh], stb + 2*A_BUF + (b_row + nh*16) * SROW + b_colb);
        #pragma unroll
        for (int mf = 0; mf < 4; mf++)
            #pragma unroll
            for (int nh = 0; nh < 4; nh++) {
                mma16816(acc[mf][2*nh],   ah4[mf], bh4[nh][0], bh4[nh][1]);
                mma16816(acc[mf][2*nh+1], ah4[mf], bh4[nh][2], bh4[nh][3]);
            }

        // ---- p2: Al * Bh (bh still live) ----
        uint32_t al4[4][4];
        #pragma unroll
        for (int mf = 0; mf < 4; mf++)
            ldsm4(al4[mf], stb + A_BUF + (a_row + mf*16) * SROW + a_colb);
        #pragma unroll
        for (int mf = 0; mf < 4; mf++)
            #pragma unroll
            for (int nh = 0; nh < 4; nh++) {
                mma16816(acc[mf][2*nh],   al4[mf], bh4[nh][0], bh4[nh][1]);
                mma16816(acc[mf][2*nh+1], al4[mf], bh4[nh][2], bh4[nh][3]);
            }

        // ---- p1: Ah * Bl (bh dead, bl loads into its slots) ----
        uint32_t bl4[4][4];
        #pragma unroll
        for (int nh = 0; nh < 4; nh++)
            ldsm4(bl4[nh], stb + 2*A_BUF + B_BUF + (b_row + nh*16) * SROW + b_colb);
        #pragma unroll
        for (int mf = 0; mf < 4; mf++)
            #pragma unroll
            for (int nh = 0; nh < 4; nh++) {
                mma16816(acc[mf][2*nh],   ah4[mf], bl4[nh][0], bl4[nh][1]);
                mma16816(acc[mf][2*nh+1], ah4[mf], bl4[nh][2], bl4[nh][3]);
            }

        // Issue loads for stage c+3 (overwrites stage c-1; reads done pre-sync)
        const int nxt = c + NSTAGE - 1;
        if (nxt < NCHUNK) {
            const int kc = nxt * 16;
            const uint32_t base = sb + (uint32_t)(nxt % NSTAGE) * STAGE_SZ;
            cp16(base + a_s,                        Ah + aoff + kc);
            cp16(base + A_BUF + a_s,                Al + aoff + kc);
            cp16(base + 2*A_BUF + b_s,              Bh + boff + kc);
            cp16(base + 2*A_BUF + b_s + 16,         Bh + boff + kc + 8);
            cp16(base + 2*A_BUF + B_BUF + b_s,      Bl + boff + kc);
            cp16(base + 2*A_BUF + B_BUF + b_s + 16, Bl + boff + kc + 8);
            CP_COMMIT();
        }
    }

    // Epilogue
    const int lrow = lane >> 2;
    const int lcol = (lane & 3) * 2;
    const int ropeMode = FUSED ? ((sec == 0) ? 1 : (sec == 1) ? 2 : 0) : 0;
    __nv_bfloat16 *Ch = nullptr, *Cl = nullptr;
    if (FUSED) {
        Ch = (sec == 0) ? QH : (sec == 1) ? KH : VH;
        Cl = (sec == 0) ? QL : (sec == 1) ? KL : VL;
    }
    #pragma unroll
    for (int mf = 0; mf < 4; mf++) {
        #pragma unroll
        for (int nf = 0; nf < 8; nf++) {
            float* cc = acc[mf][nf];
            const int col = n0 + wn*64 + nf*8 + lcol;
            #pragma unroll
            for (int hf = 0; hf < 2; hf++) {
                const int m = m0 + wm*64 + mf*16 + lrow + hf*8;
                float v1 = cc[hf*2], v2 = cc[hf*2+1];
                if (ropeMode != 0) {
                    const int s = m & (SEQ - 1);
                    float2 cs = g_tbl[s * (HDIM/2) + ((col & (HDIM-1)) >> 1)];
                    float r1 = v1*cs.x - v2*cs.y;
                    float r2 = v1*cs.y + v2*cs.x;
                    if (ropeMode == 1) { r1 *= 0.125f; r2 *= 0.125f; }
                    v1 = r1; v2 = r2;
                }
                if (FUSED) {
                    uint32_t hi, lo;
                    split2(v1, v2, hi, lo);
                    *(uint32_t*)&Ch[(size_t)m * DMODEL + col] = hi;
                    *(uint32_t*)&Cl[(size_t)m * DMODEL + col] = lo;
                } else {
                    *(float2*)&C[(size_t)m * DMODEL + col] = make_float2(v1, v2);
                }
            }
        }
    }
}

// ===========================================================================
// Tensor-core causal flash attention, split-bf16 (unchanged from round 7).
// ===========================================================================
#define ASROW 144

__global__ __launch_bounds__(128) void attn_mma_kernel()
{
    __shared__ __align__(16) char sm[4 * 64 * ASROW];
    const uint32_t sKh = smem_u32(sm);
    const uint32_t sKl = sKh + 64 * ASROW;
    const uint32_t sVh = sKl + 64 * ASROW;
    const uint32_t sVl = sVh + 64 * ASROW;

    const int tid  = threadIdx.x;
    const int wid  = tid >> 5, lane = tid & 31;
    const int bh   = blockIdx.y;
    const int b    = bh / NHEADS, h = bh % NHEADS;
    const size_t rowbase = (size_t)(b * SEQ);
    const int hc = h * HDIM;

    const int ldr = tid >> 1;
    const int ldc = (tid & 1) * 32;

    const uint32_t a_row  = (lane & 15);
    const uint32_t a_colb = (lane >> 4) * 16;
    const uint32_t b_row  = (lane & 7) + ((lane >> 4) << 3);
    const uint32_t b_colb = ((lane >> 3) & 1) * 16;
    const uint32_t v_krow  = (lane & 7) + (((lane >> 3) & 1) << 3);
    const uint32_t v_ncolb = (lane >> 4) * 16;

    for (int sidx = 0; sidx < 2; sidx++) {
        const int bx = (sidx == 0) ? (int)blockIdx.x : (31 - (int)blockIdx.x);
        const int q0 = bx * 64;
        const int nk = bx + 1;

        uint32_t qh[4][4], ql[4][4];
        {
            const __nv_bfloat16* src = &g_Qh[(rowbase + q0 + ldr) * DMODEL + hc + ldc];
            #pragma unroll
            for (int i = 0; i < 4; i++)
                *(uint4*)(sm + ldr * ASROW + ldc * 2 + i * 16) = *(const uint4*)(src + i * 8);
            __syncthreads();
            #pragma unroll
            for (int kk = 0; kk < 4; kk++)
                ldsm4(qh[kk], sKh + (wid * 16 + a_row) * ASROW + kk * 32 + a_colb);
            __syncthreads();
            const __nv_bfloat16* src2 = &g_Ql[(rowbase + q0 + ldr) * DMODEL + hc + ldc];
            #pragma unroll
            for (int i = 0; i < 4; i++)
                *(uint4*)(sm + ldr * ASROW + ldc * 2 + i * 16) = *(const uint4*)(src2 + i * 8);
            __syncthreads();
            #pragma unroll
            for (int kk = 0; kk < 4; kk++)
                ldsm4(ql[kk], sKh + (wid * 16 + a_row) * ASROW + kk * 32 + a_colb);
            __syncthreads();
        }

        float o[8][4];
        #pragma unroll
        for (int j = 0; j < 8; j++)
            #pragma unroll
            for (int i = 0; i < 4; i++) o[j][i] = 0.f;
        float m0h = -INFINITY, m1h = -INFINITY, l0 = 0.f, l1 = 0.f;

        for (int kt = 0; kt < nk; kt++) {
            const int kb = kt * 64;
            {
                const size_t srow = (rowbase + kb + ldr) * DMODEL + hc + ldc;
                const uint32_t doff = ldr * ASROW + ldc * 2;
                #pragma unroll
                for (int i = 0; i < 4; i++) {
                    *(uint4*)(sm + 0*64*ASROW + doff + i*16) = *(const uint4*)(&g_Kh[srow] + i*8);
                    *(uint4*)(sm + 1*64*ASROW + doff + i*16) = *(const uint4*)(&g_Kl[srow] + i*8);
                    *(uint4*)(sm + 2*64*ASROW + doff + i*16) = *(const uint4*)(&g_Vh[srow] + i*8);
                    *(uint4*)(sm + 3*64*ASROW + doff + i*16) = *(const uint4*)(&g_Vl[srow] + i*8);
                }
            }
            __syncthreads();

            float sc[8][4];
            #pragma unroll
            for (int j = 0; j < 8; j++)
                #pragma unroll
                for (int i = 0; i < 4; i++) sc[j][i] = 0.f;

            #pragma unroll
            for (int pass = 0; pass < 3; pass++) {
                const uint32_t (*qf)[4] = (pass == 2) ? ql : qh;
                const uint32_t kbase = (pass == 1) ? sKl : sKh;
                #pragma unroll
                for (int kk = 0; kk < 4; kk++) {
                    uint32_t bf[4][4];
                    #pragma unroll
                    for (int nt = 0; nt < 4; nt++)
                        ldsm4(bf[nt], kbase + (nt*16 + b_row) * ASROW + kk*32 + b_colb);
                    #pragma unroll
                    for (int nt = 0; nt < 4; nt++) {
                        mma16816(sc[2*nt],   qf[kk], bf[nt][0], bf[nt][1]);
                        mma16816(sc[2*nt+1], qf[kk], bf[nt][2], bf[nt][3]);
                    }
                }
            }

            const int r0 = q0 + wid*16 + (lane >> 2);
            const int r1 = r0 + 8;
            if (kt == nk - 1) {
                #pragma unroll
                for (int j = 0; j < 8; j++) {
                    const int c0 = kb + j*8 + (lane & 3)*2;
                    if (c0     > r0) sc[j][0] = -1e30f;
                    if (c0 + 1 > r0) sc[j][1] = -1e30f;
                    if (c0     > r1) sc[j][2] = -1e30f;
                    if (c0 + 1 > r1) sc[j][3] = -1e30f;
                }
            }

            float mx0 = -INFINITY, mx1 = -INFINITY;
            #pragma unroll
            for (int j = 0; j < 8; j++) {
                mx0 = fmaxf(mx0, fmaxf(sc[j][0], sc[j][1]));
                mx1 = fmaxf(mx1, fmaxf(sc[j][2], sc[j][3]));
            }
            mx0 = fmaxf(mx0, __shfl_xor_sync(0xffffffffu, mx0, 1));
            mx0 = fmaxf(mx0, __shfl_xor_sync(0xffffffffu, mx0, 2));
            mx1 = fmaxf(mx1, __shfl_xor_sync(0xffffffffu, mx1, 1));
            mx1 = fmaxf(mx1, __shfl_xor_sync(0xffffffffu, mx1, 2));
            const float nm0 = fmaxf(m0h, mx0), nm1 = fmaxf(m1h, mx1);
            const float cr0 = __expf(m0h - nm0), cr1 = __expf(m1h - nm1);
            m0h = nm0; m1h = nm1;
            l0 *= cr0; l1 *= cr1;
            #pragma unroll
            for (int j = 0; j < 8; j++) {
                o[j][0] *= cr0; o[j][1] *= cr0;
                o[j][2] *= cr1; o[j][3] *= cr1;
            }
            #pragma unroll
            for (int j = 0; j < 8; j++) {
                sc[j][0] = __expf(sc[j][0] - nm0);
                sc[j][1] = __expf(sc[j][1] - nm0);
                sc[j][2] = __expf(sc[j][2] - nm1);
                sc[j][3] = __expf(sc[j][3] - nm1);
                l0 += sc[j][0] + sc[j][1];
                l1 += sc[j][2] + sc[j][3];
            }

            uint32_t ph[4][4], pl[4][4];
            #pragma unroll
            for (int ks = 0; ks < 4; ks++) {
                split2(sc[2*ks][0],   sc[2*ks][1],   ph[ks][0], pl[ks][0]);
                split2(sc[2*ks][2],   sc[2*ks][3],   ph[ks][1], pl[ks][1]);
                split2(sc[2*ks+1][0], sc[2*ks+1][1], ph[ks][2], pl[ks][2]);
                split2(sc[2*ks+1][2], sc[2*ks+1][3], ph[ks][3], pl[ks][3]);
            }

            #pragma unroll
            for (int pass = 0; pass < 3; pass++) {
                const uint32_t (*pf)[4] = (pass == 2) ? pl : ph;
                const uint32_t vbase = (pass == 1) ? sVl : sVh;
                #pragma unroll
                for (int ks = 0; ks < 4; ks++) {
                    #pragma unroll
                    for (int nt = 0; nt < 4; nt++) {
                        uint32_t vf[4];
                        ldsm4t(vf, vbase + (ks*16 + v_krow) * ASROW + nt*32 + v_ncolb);
                        mma16816(o[2*nt],   pf[ks], vf[0], vf[1]);
                        mma16816(o[2*nt+1], pf[ks], vf[2], vf[3]);
                    }
                }
            }
            __syncthreads();
        }

        l0 += __shfl_xor_sync(0xffffffffu, l0, 1);
        l0 += __shfl_xor_sync(0xffffffffu, l0, 2);
        l1 += __shfl_xor_sync(0xffffffffu, l1, 1);
        l1 += __shfl_xor_sync(0xffffffffu, l1, 2);
        const float inv0 = 1.f / l0, inv1 = 1.f / l1;
        const size_t row0 = rowbase + q0 + wid*16 + (lane >> 2);
        const size_t row1 = row0 + 8;
        #pragma unroll
        for (int j = 0; j < 8; j++) {
            const int col = hc + j*8 + (lane & 3)*2;
            uint32_t hi, lo;
            split2(o[j][0]*inv0, o[j][1]*inv0, hi, lo);
            *(uint32_t*)&g_AOh[row0 * DMODEL + col] = hi;
            *(uint32_t*)&g_AOl[row0 * DMODEL + col] = lo;
            split2(o[j][2]*inv1, o[j][3]*inv1, hi, lo);
            *(uint32_t*)&g_AOh[row1 * DMODEL + col] = hi;
            *(uint32_t*)&g_AOl[row1 * DMODEL + col] = lo;
        }
        __syncthreads();
    }
}

// ---------------------------------------------------------------------------
extern "C" void kernel_launch(void* const* d_in, const int* in_sizes, int n_in,
                              void* d_out, int out_size)
{
    const float* x  = (const float*)d_in[0];
    const float* wq = (const float*)d_in[1];
    const float* wk = (const float*)d_in[2];
    const float* wv = (const float*)d_in[3];
    const float* wo = (const float*)d_in[4];
    float* out = (float*)d_out;

    __nv_bfloat16 *XH, *XL, *WH, *WL, *QH, *QL, *KH, *KL, *VH, *VL, *AH, *AL;
    cudaGetSymbolAddress((void**)&XH, g_xh);  cudaGetSymbolAddress((void**)&XL, g_xl);
    cudaGetSymbolAddress((void**)&WH, g_wh);  cudaGetSymbolAddress((void**)&WL, g_wl);
    cudaGetSymbolAddress((void**)&QH, g_Qh);  cudaGetSymbolAddress((void**)&QL, g_Ql);
    cudaGetSymbolAddress((void**)&KH, g_Kh);  cudaGetSymbolAddress((void**)&KL, g_Kl);
    cudaGetSymbolAddress((void**)&VH, g_Vh);  cudaGetSymbolAddress((void**)&VL, g_Vl);
    cudaGetSymbolAddress((void**)&AH, g_AOh); cudaGetSymbolAddress((void**)&AL, g_AOl);

    cudaFuncSetAttribute(gemm_db_kernel<1>, cudaFuncAttributeMaxDynamicSharedMemorySize, NSTAGE*STAGE_SZ);
    cudaFuncSetAttribute(gemm_db_kernel<0>, cudaFuncAttributeMaxDynamicSharedMemorySize, NSTAGE*STAGE_SZ);

    // ncu captures the 4th launch — keep it the fused QKV gemm.
    splitw_kernel<<<(4*(WSZ/4) + 255)/256, 256>>>(wq, wk, wv, wo);   // #1
    splitx_kernel<<<((MTOT*DMODEL/4) + 255)/256, 256>>>(x);          // #2
    rope_table_kernel<<<(SEQ*(HDIM/2) + 255)/256, 256>>>();          // #3

    gemm_db_kernel<1><<<dim3(9, MTOT/128), 256, NSTAGE*STAGE_SZ>>>(
        XH, XL, WH, WL, QH, QL, KH, KL, VH, VL, nullptr);            // #4 (ncu)

    attn_mma_kernel<<<dim3(16, BATCH*NHEADS), 128>>>();              // #5

    gemm_db_kernel<0><<<dim3(3, MTOT/128), 256, NSTAGE*STAGE_SZ>>>(
        AH, AL, WH + 3*WSZ, WL + 3*WSZ,
        nullptr, nullptr, nullptr, nullptr, nullptr, nullptr, out);  // #6
}

// round 16
// speedup vs baseline: 1.2063x; 1.2063x over previous
#include <cuda_runtime.h>
#include <cuda_bf16.h>
#include <math.h>
#include <cstdint>

#define BATCH   4
#define SEQ     2048
#define DMODEL  768
#define NHEADS  12
#define HDIM    64
#define MTOT    (BATCH*SEQ)   /* 8192 */
#define WSZ     (DMODEL*DMODEL)

// Scratch (static device arrays: allocation-free per harness rules)
__device__ float2 g_tbl[SEQ*(HDIM/2)];
__device__ __nv_bfloat16 g_xh[MTOT*DMODEL], g_xl[MTOT*DMODEL];
__device__ __nv_bfloat16 g_wh[4*WSZ],       g_wl[4*WSZ];
__device__ __nv_bfloat16 g_Qh[MTOT*DMODEL], g_Ql[MTOT*DMODEL];
__device__ __nv_bfloat16 g_Kh[MTOT*DMODEL], g_Kl[MTOT*DMODEL];
__device__ __nv_bfloat16 g_Vh[MTOT*DMODEL], g_Vl[MTOT*DMODEL];
__device__ __nv_bfloat16 g_AOh[MTOT*DMODEL], g_AOl[MTOT*DMODEL];

// ===========================================================================
// Helpers
// ===========================================================================
__device__ __forceinline__ uint32_t smem_u32(const void* p) {
    uint32_t a;
    asm("{ .reg .u64 t; cvta.to.shared.u64 t, %1; cvt.u32.u64 %0, t; }" : "=r"(a) : "l"(p));
    return a;
}
__device__ __forceinline__ void ldsm4(uint32_t* r, uint32_t addr) {
    asm volatile("ldmatrix.sync.aligned.m8n8.x4.shared.b16 {%0,%1,%2,%3}, [%4];"
        : "=r"(r[0]), "=r"(r[1]), "=r"(r[2]), "=r"(r[3]) : "r"(addr));
}
__device__ __forceinline__ void ldsm4t(uint32_t* r, uint32_t addr) {
    asm volatile("ldmatrix.sync.aligned.m8n8.x4.trans.shared.b16 {%0,%1,%2,%3}, [%4];"
        : "=r"(r[0]), "=r"(r[1]), "=r"(r[2]), "=r"(r[3]) : "r"(addr));
}
__device__ __forceinline__ void mma16816(float* c, const uint32_t* a, uint32_t b0, uint32_t b1) {
    asm volatile("mma.sync.aligned.m16n8k16.row.col.f32.bf16.bf16.f32 "
        "{%0,%1,%2,%3}, {%4,%5,%6,%7}, {%8,%9}, {%0,%1,%2,%3};"
        : "+f"(c[0]), "+f"(c[1]), "+f"(c[2]), "+f"(c[3])
        : "r"(a[0]), "r"(a[1]), "r"(a[2]), "r"(a[3]), "r"(b0), "r"(b1));
}
__device__ __forceinline__ uint32_t pack2(float x, float y) {
    __nv_bfloat16 hx = __float2bfloat16(x), hy = __float2bfloat16(y);
    return (uint32_t)__bfloat16_as_ushort(hx) | ((uint32_t)__bfloat16_as_ushort(hy) << 16);
}
__device__ __forceinline__ void split2(float x, float y, uint32_t& hi, uint32_t& lo) {
    __nv_bfloat16 hx = __float2bfloat16(x), hy = __float2bfloat16(y);
    hi = (uint32_t)__bfloat16_as_ushort(hx) | ((uint32_t)__bfloat16_as_ushort(hy) << 16);
    lo = pack2(x - __bfloat162float(hx), y - __bfloat162float(hy));
}
__device__ __forceinline__ void cp16(uint32_t dst, const void* src) {
    asm volatile("cp.async.cg.shared.global [%0], [%1], 16;" :: "r"(dst), "l"(src) : "memory");
}
#define CP_COMMIT() asm volatile("cp.async.commit_group;" ::: "memory")
#define CP_WAIT(n)  asm volatile("cp.async.wait_group %0;" :: "n"(n) : "memory")

// ---------------------------------------------------------------------------
// RoPE table (fp64-accurate sincos)
// ---------------------------------------------------------------------------
__global__ void rope_table_kernel()
{
    int idx = blockIdx.x * blockDim.x + threadIdx.x;
    if (idx >= SEQ * (HDIM/2)) return;
    int s = idx >> 5, j = idx & 31;
    float invf = (float)pow(10000.0, -(double)(2*j) / (double)HDIM);
    float angf = (float)s * invf;
    double sn, cs;
    sincos((double)angf, &sn, &cs);
    g_tbl[idx] = make_float2((float)cs, (float)sn);
}

// ---------------------------------------------------------------------------
// hi/lo bf16 splits: x AND all 4 weights in ONE kernel (launch-count control)
// ---------------------------------------------------------------------------
__device__ __forceinline__ void split4v(float4 v, uint2& hi, uint2& lo)
{
    split2(v.x, v.y, hi.x, lo.x);
    split2(v.z, v.w, hi.y, lo.y);
}
__global__ void splits_all_kernel(const float* __restrict__ x,
                                  const float* __restrict__ w0, const float* __restrict__ w1,
                                  const float* __restrict__ w2, const float* __restrict__ w3)
{
    const int xn4 = MTOT * DMODEL / 4;
    const int wn4 = WSZ / 4;
    int i = blockIdx.x * blockDim.x + threadIdx.x;
    uint2 h, l;
    if (i < xn4) {
        split4v(((const float4*)x)[i], h, l);
        ((uint2*)g_xh)[i] = h;
        ((uint2*)g_xl)[i] = l;
    } else {
        int j = i - xn4;
        if (j >= 4 * wn4) return;
        int ws = j / wn4, off = j - ws * wn4;
        const float* src = (ws == 0) ? w0 : (ws == 1) ? w1 : (ws == 2) ? w2 : w3;
        split4v(((const float4*)src)[off], h, l);
        ((uint2*)g_wh)[j] = h;
        ((uint2*)g_wl)[j] = l;
    }
}

// ===========================================================================
// 4-stage cp.async split-bf16 tensor-core GEMM (round-11 config: measured
// best — 128x128 tile, 2 CTAs/SM, ldsm reuse, single sync per chunk).
// FUSED=1: QKV fused, grid (18,64). FUSED=0: WO, fp32 out, grid (6,64).
// ===========================================================================
#define SROW     48
#define BUF_SZ   (128*SROW)         /* 6144  */
#define STAGE_SZ (4*BUF_SZ)         /* 24576 */
#define NSTAGE   4
#define NCHUNK   (DMODEL/16)        /* 48    */

__device__ __forceinline__ void stage_load(uint32_t base, uint32_t soff,
    const __nv_bfloat16* pAh, const __nv_bfloat16* pAl,
    const __nv_bfloat16* pBh, const __nv_bfloat16* pBl)
{
    cp16(base + 0*BUF_SZ + soff, pAh);
    cp16(base + 1*BUF_SZ + soff, pAl);
    cp16(base + 2*BUF_SZ + soff, pBh);
    cp16(base + 3*BUF_SZ + soff, pBl);
}

template<int FUSED>
__global__ __launch_bounds__(256) void gemm_db_kernel(
    const __nv_bfloat16* __restrict__ Ah, const __nv_bfloat16* __restrict__ Al,
    const __nv_bfloat16* __restrict__ Bh0, const __nv_bfloat16* __restrict__ Bl0,
    __nv_bfloat16* __restrict__ QH, __nv_bfloat16* __restrict__ QL,
    __nv_bfloat16* __restrict__ KH, __nv_bfloat16* __restrict__ KL,
    __nv_bfloat16* __restrict__ VH, __nv_bfloat16* __restrict__ VL,
    float* __restrict__ C)
{
    extern __shared__ __align__(16) char sm[];
    const uint32_t sb = smem_u32(sm);

    const int tid = threadIdx.x;
    const int wid = tid >> 5, lane = tid & 31;
    const int wm  = wid >> 2, wn = wid & 3;
    const int m0  = blockIdx.y * 128;

    int sec, nx;
    if (FUSED) { sec = blockIdx.x / 6; nx = blockIdx.x % 6; }
    else       { sec = 0;              nx = blockIdx.x;     }
    const int n0 = nx * 128;
    const __nv_bfloat16* Bh = Bh0 + (size_t)sec * WSZ;
    const __nv_bfloat16* Bl = Bl0 + (size_t)sec * WSZ;

    const int r    = tid >> 1;
    const int half = (tid & 1) * 8;
    const size_t aoff = (size_t)(m0 + r) * DMODEL + half;
    const size_t boff = (size_t)(n0 + r) * DMODEL + half;
    const uint32_t soff = (uint32_t)(r * SROW + half * 2);

    const uint32_t a_row  = wm * 64 + (lane & 15);
    const uint32_t a_colb = (lane >> 4) * 16;
    const uint32_t b_row  = wn * 32 + (lane & 7) + ((lane >> 4) << 3);
    const uint32_t b_colb = ((lane >> 3) & 1) * 16;

    float acc[4][4][4] = {};

    #pragma unroll
    for (int s = 0; s < NSTAGE - 1; s++) {
        const int kc = s * 16;
        stage_load(sb + s * STAGE_SZ, soff,
                   Ah + aoff + kc, Al + aoff + kc, Bh + boff + kc, Bl + boff + kc);
        CP_COMMIT();
    }

    for (int c = 0; c < NCHUNK; c++) {
        const uint32_t stb = sb + (uint32_t)(c % NSTAGE) * STAGE_SZ;

        if (c + 2 < NCHUNK)      CP_WAIT(2);
        else if (c + 1 < NCHUNK) CP_WAIT(1);
        else                     CP_WAIT(0);
        __syncthreads();

        uint32_t ah[4][4], bh[2][4], bl[2][4];
        #pragma unroll
        for (int mf = 0; mf < 4; mf++)
            ldsm4(ah[mf], stb + 0*BUF_SZ + (a_row + mf*16) * SROW + a_colb);
        #pragma unroll
        for (int nh = 0; nh < 2; nh++)
            ldsm4(bh[nh], stb + 2*BUF_SZ + (b_row + nh*16) * SROW + b_colb);
        #pragma unroll
        for (int nh = 0; nh < 2; nh++)
            ldsm4(bl[nh], stb + 3*BUF_SZ + (b_row + nh*16) * SROW + b_colb);

        #pragma unroll
        for (int mf = 0; mf < 4; mf++) {          // p0: Ah * Bh
            #pragma unroll
            for (int nh = 0; nh < 2; nh++) {
                mma16816(acc[mf][2*nh],   ah[mf], bh[nh][0], bh[nh][1]);
                mma16816(acc[mf][2*nh+1], ah[mf], bh[nh][2], bh[nh][3]);
            }
        }
        #pragma unroll
        for (int mf = 0; mf < 4; mf++) {          // p1: Ah * Bl
            #pragma unroll
            for (int nh = 0; nh < 2; nh++) {
                mma16816(acc[mf][2*nh],   ah[mf], bl[nh][0], bl[nh][1]);
                mma16816(acc[mf][2*nh+1], ah[mf], bl[nh][2], bl[nh][3]);
            }
        }
        uint32_t al[4][4];
        #pragma unroll
        for (int mf = 0; mf < 4; mf++)
            ldsm4(al[mf], stb + 1*BUF_SZ + (a_row + mf*16) * SROW + a_colb);
        #pragma unroll
        for (int mf = 0; mf < 4; mf++) {          // p2: Al * Bh
            #pragma unroll
            for (int nh = 0; nh < 2; nh++) {
                mma16816(acc[mf][2*nh],   al[mf], bh[nh][0], bh[nh][1]);
                mma16816(acc[mf][2*nh+1], al[mf], bh[nh][2], bh[nh][3]);
            }
        }

        const int nxt = c + NSTAGE - 1;
        if (nxt < NCHUNK) {
            const int kc = nxt * 16;
            stage_load(sb + (uint32_t)(nxt % NSTAGE) * STAGE_SZ, soff,
                       Ah + aoff + kc, Al + aoff + kc, Bh + boff + kc, Bl + boff + kc);
            CP_COMMIT();
        }
    }

    // Epilogue
    const int lrow = lane >> 2;
    const int lcol = (lane & 3) * 2;
    const int ropeMode = FUSED ? ((sec == 0) ? 1 : (sec == 1) ? 2 : 0) : 0;
    __nv_bfloat16 *Ch = nullptr, *Cl = nullptr;
    if (FUSED) {
        Ch = (sec == 0) ? QH : (sec == 1) ? KH : VH;
        Cl = (sec == 0) ? QL : (sec == 1) ? KL : VL;
    }
    #pragma unroll
    for (int mf = 0; mf < 4; mf++) {
        #pragma unroll
        for (int nf = 0; nf < 4; nf++) {
            float* cc = acc[mf][nf];
            const int col = n0 + wn*32 + nf*8 + lcol;
            #pragma unroll
            for (int hf = 0; hf < 2; hf++) {
                const int m = m0 + wm*64 + mf*16 + lrow + hf*8;
                float v1 = cc[hf*2], v2 = cc[hf*2+1];
                if (ropeMode != 0) {
                    const int s = m & (SEQ - 1);
                    float2 cs = g_tbl[s * (HDIM/2) + ((col & (HDIM-1)) >> 1)];
                    float r1 = v1*cs.x - v2*cs.y;
                    float r2 = v1*cs.y + v2*cs.x;
                    if (ropeMode == 1) { r1 *= 0.125f; r2 *= 0.125f; }
                    v1 = r1; v2 = r2;
                }
                if (FUSED) {
                    uint32_t hi, lo;
                    split2(v1, v2, hi, lo);
                    *(uint32_t*)&Ch[(size_t)m * DMODEL + col] = hi;
                    *(uint32_t*)&Cl[(size_t)m * DMODEL + col] = lo;
                } else {
                    *(float2*)&C[(size_t)m * DMODEL + col] = make_float2(v1, v2);
                }
            }
        }
    }
}

// ===========================================================================
// Tensor-core causal flash attention, split-bf16.
// ROUND-16 CHANGE: fragment reuse across split passes (same trick as the
// gemm). QK: load Kh frags once -> qh*Kh + ql*Kh, then Kl -> qh*Kl.
// PV: load Vh frags once -> ph*Vh + pl*Vh, then Vl -> ph*Vl.
// ldsm per tile per warp: 96 -> 64 (-33% smem crossbar).
// ===========================================================================
#define ASROW 144

__global__ __launch_bounds__(128) void attn_mma_kernel()
{
    __shared__ __align__(16) char sm[4 * 64 * ASROW];
    const uint32_t sKh = smem_u32(sm);
    const uint32_t sKl = sKh + 64 * ASROW;
    const uint32_t sVh = sKl + 64 * ASROW;
    const uint32_t sVl = sVh + 64 * ASROW;

    const int tid  = threadIdx.x;
    const int wid  = tid >> 5, lane = tid & 31;
    const int bh_  = blockIdx.y;
    const int b    = bh_ / NHEADS, h = bh_ % NHEADS;
    const size_t rowbase = (size_t)(b * SEQ);
    const int hc = h * HDIM;

    const int ldr = tid >> 1;
    const int ldc = (tid & 1) * 32;

    const uint32_t a_row  = (lane & 15);
    const uint32_t a_colb = (lane >> 4) * 16;
    const uint32_t b_row  = (lane & 7) + ((lane >> 4) << 3);
    const uint32_t b_colb = ((lane >> 3) & 1) * 16;
    const uint32_t v_krow  = (lane & 7) + (((lane >> 3) & 1) << 3);
    const uint32_t v_ncolb = (lane >> 4) * 16;

    for (int sidx = 0; sidx < 2; sidx++) {
        const int bx = (sidx == 0) ? (int)blockIdx.x : (31 - (int)blockIdx.x);
        const int q0 = bx * 64;
        const int nk = bx + 1;

        uint32_t qh[4][4], ql[4][4];
        {
            const __nv_bfloat16* src = &g_Qh[(rowbase + q0 + ldr) * DMODEL + hc + ldc];
            #pragma unroll
            for (int i = 0; i < 4; i++)
                *(uint4*)(sm + ldr * ASROW + ldc * 2 + i * 16) = *(const uint4*)(src + i * 8);
            __syncthreads();
            #pragma unroll
            for (int kk = 0; kk < 4; kk++)
                ldsm4(qh[kk], sKh + (wid * 16 + a_row) * ASROW + kk * 32 + a_colb);
            __syncthreads();
            const __nv_bfloat16* src2 = &g_Ql[(rowbase + q0 + ldr) * DMODEL + hc + ldc];
            #pragma unroll
            for (int i = 0; i < 4; i++)
                *(uint4*)(sm + ldr * ASROW + ldc * 2 + i * 16) = *(const uint4*)(src2 + i * 8);
            __syncthreads();
            #pragma unroll
            for (int kk = 0; kk < 4; kk++)
                ldsm4(ql[kk], sKh + (wid * 16 + a_row) * ASROW + kk * 32 + a_colb);
            __syncthreads();
        }

        float o[8][4];
        #pragma unroll
        for (int j = 0; j < 8; j++)
            #pragma unroll
            for (int i = 0; i < 4; i++) o[j][i] = 0.f;
        float m0h = -INFINITY, m1h = -INFINITY, l0 = 0.f, l1 = 0.f;

        for (int kt = 0; kt < nk; kt++) {
            const int kb = kt * 64;
            {
                const size_t srow = (rowbase + kb + ldr) * DMODEL + hc + ldc;
                const uint32_t doff = ldr * ASROW + ldc * 2;
                #pragma unroll
                for (int i = 0; i < 4; i++) {
                    *(uint4*)(sm + 0*64*ASROW + doff + i*16) = *(const uint4*)(&g_Kh[srow] + i*8);
                    *(uint4*)(sm + 1*64*ASROW + doff + i*16) = *(const uint4*)(&g_Kl[srow] + i*8);
                    *(uint4*)(sm + 2*64*ASROW + doff + i*16) = *(const uint4*)(&g_Vh[srow] + i*8);
                    *(uint4*)(sm + 3*64*ASROW + doff + i*16) = *(const uint4*)(&g_Vl[srow] + i*8);
                }
            }
            __syncthreads();

            float sc[8][4];
            #pragma unroll
            for (int j = 0; j < 8; j++)
                #pragma unroll
                for (int i = 0; i < 4; i++) sc[j][i] = 0.f;

            // ---- S = Q K^T with K-fragment reuse ----
            #pragma unroll
            for (int kk = 0; kk < 4; kk++) {          // Kh: used by qh AND ql
                uint32_t bf[4][4];
                #pragma unroll
                for (int nt = 0; nt < 4; nt++)
                    ldsm4(bf[nt], sKh + (nt*16 + b_row) * ASROW + kk*32 + b_colb);
                #pragma unroll
                for (int nt = 0; nt < 4; nt++) {
                    mma16816(sc[2*nt],   qh[kk], bf[nt][0], bf[nt][1]);
                    mma16816(sc[2*nt+1], qh[kk], bf[nt][2], bf[nt][3]);
                    mma16816(sc[2*nt],   ql[kk], bf[nt][0], bf[nt][1]);
                    mma16816(sc[2*nt+1], ql[kk], bf[nt][2], bf[nt][3]);
                }
            }
            #pragma unroll
            for (int kk = 0; kk < 4; kk++) {          // Kl: used by qh only
                uint32_t bf[4][4];
                #pragma unroll
                for (int nt = 0; nt < 4; nt++)
                    ldsm4(bf[nt], sKl + (nt*16 + b_row) * ASROW + kk*32 + b_colb);
                #pragma unroll
                for (int nt = 0; nt < 4; nt++) {
                    mma16816(sc[2*nt],   qh[kk], bf[nt][0], bf[nt][1]);
                    mma16816(sc[2*nt+1], qh[kk], bf[nt][2], bf[nt][3]);
                }
            }

            const int r0 = q0 + wid*16 + (lane >> 2);
            const int r1 = r0 + 8;
            if (kt == nk - 1) {
                #pragma unroll
                for (int j = 0; j < 8; j++) {
                    const int c0 = kb + j*8 + (lane & 3)*2;
                    if (c0     > r0) sc[j][0] = -1e30f;
                    if (c0 + 1 > r0) sc[j][1] = -1e30f;
                    if (c0     > r1) sc[j][2] = -1e30f;
                    if (c0 + 1 > r1) sc[j][3] = -1e30f;
                }
            }

            float mx0 = -INFINITY, mx1 = -INFINITY;
            #pragma unroll
            for (int j = 0; j < 8; j++) {
                mx0 = fmaxf(mx0, fmaxf(sc[j][0], sc[j][1]));
                mx1 = fmaxf(mx1, fmaxf(sc[j][2], sc[j][3]));
            }
            mx0 = fmaxf(mx0, __shfl_xor_sync(0xffffffffu, mx0, 1));
            mx0 = fmaxf(mx0, __shfl_xor_sync(0xffffffffu, mx0, 2));
            mx1 = fmaxf(mx1, __shfl_xor_sync(0xffffffffu, mx1, 1));
            mx1 = fmaxf(mx1, __shfl_xor_sync(0xffffffffu, mx1, 2));
            const float nm0 = fmaxf(m0h, mx0), nm1 = fmaxf(m1h, mx1);
            const float cr0 = __expf(m0h - nm0), cr1 = __expf(m1h - nm1);
            m0h = nm0; m1h = nm1;
            l0 *= cr0; l1 *= cr1;
            #pragma unroll
            for (int j = 0; j < 8; j++) {
                o[j][0] *= cr0; o[j][1] *= cr0;
                o[j][2] *= cr1; o[j][3] *= cr1;
            }
            #pragma unroll
            for (int j = 0; j < 8; j++) {
                sc[j][0] = __expf(sc[j][0] - nm0);
                sc[j][1] = __expf(sc[j][1] - nm0);
                sc[j][2] = __expf(sc[j][2] - nm1);
                sc[j][3] = __expf(sc[j][3] - nm1);
                l0 += sc[j][0] + sc[j][1];
                l1 += sc[j][2] + sc[j][3];
            }

            uint32_t ph[4][4], pl[4][4];
            #pragma unroll
            for (int ks = 0; ks < 4; ks++) {
                split2(sc[2*ks][0],   sc[2*ks][1],   ph[ks][0], pl[ks][0]);
                split2(sc[2*ks][2],   sc[2*ks][3],   ph[ks][1], pl[ks][1]);
                split2(sc[2*ks+1][0], sc[2*ks+1][1], ph[ks][2], pl[ks][2]);
                split2(sc[2*ks+1][2], sc[2*ks+1][3], ph[ks][3], pl[ks][3]);
            }

            // ---- O += P V with V-fragment reuse ----
            #pragma unroll
            for (int ks = 0; ks < 4; ks++) {          // Vh: used by ph AND pl
                #pragma unroll
                for (int nt = 0; nt < 4; nt++) {
                    uint32_t vf[4];
                    ldsm4t(vf, sVh + (ks*16 + v_krow) * ASROW + nt*32 + v_ncolb);
                    mma16816(o[2*nt],   ph[ks], vf[0], vf[1]);
                    mma16816(o[2*nt+1], ph[ks], vf[2], vf[3]);
                    mma16816(o[2*nt],   pl[ks], vf[0], vf[1]);
                    mma16816(o[2*nt+1], pl[ks], vf[2], vf[3]);
                }
            }
            #pragma unroll
            for (int ks = 0; ks < 4; ks++) {          // Vl: used by ph only
                #pragma unroll
                for (int nt = 0; nt < 4; nt++) {
                    uint32_t vf[4];
                    ldsm4t(vf, sVl + (ks*16 + v_krow) * ASROW + nt*32 + v_ncolb);
                    mma16816(o[2*nt],   ph[ks], vf[0], vf[1]);
                    mma16816(o[2*nt+1], ph[ks], vf[2], vf[3]);
                }
            }
            __syncthreads();
        }

        l0 += __shfl_xor_sync(0xffffffffu, l0, 1);
        l0 += __shfl_xor_sync(0xffffffffu, l0, 2);
        l1 += __shfl_xor_sync(0xffffffffu, l1, 1);
        l1 += __shfl_xor_sync(0xffffffffu, l1, 2);
        const float inv0 = 1.f / l0, inv1 = 1.f / l1;
        const size_t row0 = rowbase + q0 + wid*16 + (lane >> 2);
        const size_t row1 = row0 + 8;
        #pragma unroll
        for (int j = 0; j < 8; j++) {
            const int col = hc + j*8 + (lane & 3)*2;
            uint32_t hi, lo;
            split2(o[j][0]*inv0, o[j][1]*inv0, hi, lo);
            *(uint32_t*)&g_AOh[row0 * DMODEL + col] = hi;
            *(uint32_t*)&g_AOl[row0 * DMODEL + col] = lo;
            split2(o[j][2]*inv1, o[j][3]*inv1, hi, lo);
            *(uint32_t*)&g_AOh[row1 * DMODEL + col] = hi;
            *(uint32_t*)&g_AOl[row1 * DMODEL + col] = lo;
        }
        __syncthreads();
    }
}

// ---------------------------------------------------------------------------
extern "C" void kernel_launch(void* const* d_in, const int* in_sizes, int n_in,
                              void* d_out, int out_size)
{
    const float* x  = (const float*)d_in[0];
    const float* wq = (const float*)d_in[1];
    const float* wk = (const float*)d_in[2];
    const float* wv = (const float*)d_in[3];
    const float* wo = (const float*)d_in[4];
    float* out = (float*)d_out;

    __nv_bfloat16 *XH, *XL, *WH, *WL, *QH, *QL, *KH, *KL, *VH, *VL, *AH, *AL;
    cudaGetSymbolAddress((void**)&XH, g_xh);  cudaGetSymbolAddress((void**)&XL, g_xl);
    cudaGetSymbolAddress((void**)&WH, g_wh);  cudaGetSymbolAddress((void**)&WL, g_wl);
    cudaGetSymbolAddress((void**)&QH, g_Qh);  cudaGetSymbolAddress((void**)&QL, g_Ql);
    cudaGetSymbolAddress((void**)&KH, g_Kh);  cudaGetSymbolAddress((void**)&KL, g_Kl);
    cudaGetSymbolAddress((void**)&VH, g_Vh);  cudaGetSymbolAddress((void**)&VL, g_Vl);
    cudaGetSymbolAddress((void**)&AH, g_AOh); cudaGetSymbolAddress((void**)&AL, g_AOl);

    cudaFuncSetAttribute(gemm_db_kernel<1>, cudaFuncAttributeMaxDynamicSharedMemorySize, NSTAGE*STAGE_SZ);
    cudaFuncSetAttribute(gemm_db_kernel<0>, cudaFuncAttributeMaxDynamicSharedMemorySize, NSTAGE*STAGE_SZ);

    const int tot4 = MTOT*DMODEL/4 + 4*(WSZ/4);

    // ncu captures the 4th launch — make it attention this round.
    splits_all_kernel<<<(tot4 + 255)/256, 256>>>(x, wq, wk, wv, wo);  // #1
    rope_table_kernel<<<(SEQ*(HDIM/2) + 255)/256, 256>>>();           // #2

    gemm_db_kernel<1><<<dim3(18, MTOT/128), 256, NSTAGE*STAGE_SZ>>>(
        XH, XL, WH, WL, QH, QL, KH, KL, VH, VL, nullptr);             // #3

    attn_mma_kernel<<<dim3(16, BATCH*NHEADS), 128>>>();               // #4 (ncu)

    gemm_db_kernel<0><<<dim3(6, MTOT/128), 256, NSTAGE*STAGE_SZ>>>(
        AH, AL, WH + 3*WSZ, WL + 3*WSZ,
        nullptr, nullptr, nullptr, nullptr, nullptr, nullptr, out);   // #5
}